// round 7
// baseline (speedup 1.0000x reference)
#include <cuda_runtime.h>
#include <cstddef>

#define IMG 512
#define TILE_X 64
#define TILE_Y 128
#define IN_X 72          // aligned 72-col window, col0a = 64*bx - 4
#define IN_Y 134         // 128 + 6 halo rows
#define NV4 18           // float4 per smem row

__constant__ float c_w[49];

// ---- packed f32x2 helpers (sm_103a) ----
__device__ __forceinline__ unsigned long long pk2(float lo, float hi) {
    unsigned long long r;
    asm("mov.b64 %0, {%1, %2};" : "=l"(r) : "f"(lo), "f"(hi));
    return r;
}
__device__ __forceinline__ void vfma(unsigned long long& d,
                                     unsigned long long a,
                                     unsigned long long b) {
    asm("fma.rn.f32x2 %0, %1, %2, %0;" : "+l"(d) : "l"(a), "l"(b));
}
__device__ __forceinline__ void unpk2(unsigned long long v, float& lo, float& hi) {
    asm("mov.b64 {%0, %1}, %2;" : "=f"(lo), "=f"(hi) : "l"(v));
}

__global__ __launch_bounds__(256, 3)
void conv7x7_kernel(const float* __restrict__ x,
                    float* __restrict__ out)
{
    __shared__ float s[IN_Y][IN_X];   // 134*72*4 = 38,592 B

    const int b     = blockIdx.z;
    const int row0  = blockIdx.y * TILE_Y - 3;
    const int col0a = blockIdx.x * TILE_X - 4;   // 4-aligned window start
    const int tid   = threadIdx.x;

    const float* __restrict__ xb = x + (size_t)b * IMG * IMG;

    // Vectorized halo-tile load: each float4 fully in- or out-of-range.
    for (int i = tid; i < IN_Y * NV4; i += 256) {
        int r  = i / NV4;
        int c4 = i - r * NV4;
        int gr = row0 + r;
        int gc = col0a + 4 * c4;
        float4 v = make_float4(0.f, 0.f, 0.f, 0.f);
        if ((unsigned)gr < (unsigned)IMG && (unsigned)gc < (unsigned)IMG)
            v = *reinterpret_cast<const float4*>(&xb[(size_t)gr * IMG + gc]);
        *reinterpret_cast<float4*>(&s[r][4 * c4]) = v;
    }

    __syncthreads();

    const int txc = tid & 15;    // output cols 4*txc .. 4*txc+3 (local)
    const int tyc = tid >> 4;    // output rows 8*tyc .. 8*tyc+7 (local)

    // vacc[oy][p] = packed accumulator for output cols (4*txc + 2p, +2p+1)
    unsigned long long vacc[8][2];
#pragma unroll
    for (int oy = 0; oy < 8; oy++) { vacc[oy][0] = 0ULL; vacc[oy][1] = 0ULL; }

    // 14 smem rows feed this thread's 8 output rows.
#pragma unroll
    for (int iy = 0; iy < 14; iy++) {
        float rbuf[12];
        const float* sp = &s[8 * tyc + iy][4 * txc];
#pragma unroll
        for (int j = 0; j < 3; j++) {
            float4 v = *reinterpret_cast<const float4*>(sp + 4 * j);
            rbuf[4 * j + 0] = v.x;
            rbuf[4 * j + 1] = v.y;
            rbuf[4 * j + 2] = v.z;
            rbuf[4 * j + 3] = v.w;
        }

        // Adjacent data pairs dp[i] = (rbuf[i], rbuf[i+1]), needed i = 1..9.
        unsigned long long dp[10];
#pragma unroll
        for (int i = 1; i <= 9; i++) dp[i] = pk2(rbuf[i], rbuf[i + 1]);

#pragma unroll
        for (int oy = 0; oy < 8; oy++) {
            const int ky = iy - oy;
            if (ky >= 0 && ky < 7) {
#pragma unroll
                for (int kx = 0; kx < 7; kx++) {
                    // replicated weight pair — constant idx, hoisted/CSEd
                    const float wv = c_w[ky * 7 + kx];
                    const unsigned long long wp = pk2(wv, wv);
                    vfma(vacc[oy][0], wp, dp[1 + kx]);   // cols +0,+1
                    vfma(vacc[oy][1], wp, dp[3 + kx]);   // cols +2,+3
                }
            }
        }
    }

    // Epilogue: unpack pairs straight into the float4 store (no hadd).
    float* ob = out + (size_t)b * IMG * IMG
              + (size_t)(blockIdx.y * TILE_Y + 8 * tyc) * IMG
              + blockIdx.x * TILE_X + 4 * txc;
#pragma unroll
    for (int oy = 0; oy < 8; oy++) {
        float4 v;
        unpk2(vacc[oy][0], v.x, v.y);
        unpk2(vacc[oy][1], v.z, v.w);
        *reinterpret_cast<float4*>(ob + (size_t)oy * IMG) = v;
    }
}

extern "C" void kernel_launch(void* const* d_in, const int* in_sizes, int n_in,
                              void* d_out, int out_size)
{
    const float* x = (const float*)d_in[0];   // (64, 512, 512) fp32
    const float* w = (const float*)d_in[1];   // (7, 7) fp32
    float* out = (float*)d_out;               // (64, 512, 512) fp32

    cudaMemcpyToSymbolAsync(c_w, w, 49 * sizeof(float), 0,
                            cudaMemcpyDeviceToDevice, 0);

    dim3 grid(IMG / TILE_X, IMG / TILE_Y, 64);   // 8 x 4 x 64 = 2048 CTAs
    conv7x7_kernel<<<grid, 256>>>(x, out);
}

// round 12
// speedup vs baseline: 1.3290x; 1.3290x over previous
#include <cuda_runtime.h>
#include <cstdint>
#include <cstddef>

#define IMG 512
#define TILE_Y 128
#define TILE_X 64
#define IN_ROWS 134      // 128 + 6 halo
#define PITCH 76         // smem pitch: 76%32=12 -> conflict-free frag loads
#define NV4 18           // 72-col aligned window, col0a = 64*bx - 4

__constant__ float c_w[49];

__device__ __forceinline__ uint32_t f2tf32(float v) {
    uint32_t r;
    asm("cvt.rna.tf32.f32 %0, %1;" : "=r"(r) : "f"(v));
    return r;
}

// D(16x8,f32) += A(16x8,tf32,row) * B(8x8,tf32,col)
__device__ __forceinline__ void mma8(float* d, const uint32_t* a, const uint32_t* b) {
    asm volatile(
        "mma.sync.aligned.m16n8k8.row.col.f32.tf32.tf32.f32 "
        "{%0,%1,%2,%3}, {%4,%5,%6,%7}, {%8,%9}, {%0,%1,%2,%3};"
        : "+f"(d[0]), "+f"(d[1]), "+f"(d[2]), "+f"(d[3])
        : "r"(a[0]), "r"(a[1]), "r"(a[2]), "r"(a[3]), "r"(b[0]), "r"(b[1]));
}

__global__ __launch_bounds__(256, 4)
void conv7x7_mma_kernel(const float* __restrict__ x, float* __restrict__ out)
{
    __shared__ uint32_t tile[IN_ROWS][PITCH];   // tf32 bits of input window
    __shared__ uint32_t btab[7][2][8][8];       // tf32 Toeplitz weight tiles

    const int tid   = threadIdx.x;
    const int b     = blockIdx.z;
    const int row0  = blockIdx.y * TILE_Y - 3;
    const int col0a = blockIdx.x * TILE_X - 4;   // 4-aligned window start

    const float* __restrict__ xb = x + (size_t)b * IMG * IMG;

    // ---- prologue: tile load (float4, zero-pad OOB) + convert to tf32 ----
    for (int i = tid; i < IN_ROWS * NV4; i += 256) {
        int r  = i / NV4;
        int c4 = i - r * NV4;
        int gr = row0 + r;
        int gc = col0a + 4 * c4;
        float4 v = make_float4(0.f, 0.f, 0.f, 0.f);
        if ((unsigned)gr < (unsigned)IMG && (unsigned)gc < (unsigned)IMG)
            v = *reinterpret_cast<const float4*>(&xb[(size_t)gr * IMG + gc]);
        uint4 u = make_uint4(f2tf32(v.x), f2tf32(v.y), f2tf32(v.z), f2tf32(v.w));
        *reinterpret_cast<uint4*>(&tile[r][4 * c4]) = u;
    }

    // ---- Toeplitz B tables: B0[k][n]=w[ky][k-n-1], B1[k][n]=w[ky][k-n+7] ----
    for (int i = tid; i < 7 * 2 * 8 * 8; i += 256) {
        int ky  = i >> 7;
        int var = (i >> 6) & 1;
        int k   = (i >> 3) & 7;
        int n   = i & 7;
        int kx  = var ? (k - n + 7) : (k - n - 1);
        float wv = ((unsigned)kx < 7u) ? c_w[ky * 7 + kx] : 0.0f;
        btab[ky][var][k][n] = f2tf32(wv);
    }
    __syncthreads();

    const int lane = tid & 31;
    const int wid  = tid >> 5;     // warp -> output rows 16*wid .. 16*wid+15
    const int grp  = lane >> 2;    // 0..7
    const int tq   = lane & 3;     // 0..3

    float acc[8][4] = {};          // 8 n-tiles x 4 fp32 frag regs

    for (int ky = 0; ky < 7; ky++) {
        uint32_t b0[2], b1[2];
        b0[0] = btab[ky][0][tq][grp];
        b0[1] = btab[ky][0][tq + 4][grp];
        b1[0] = btab[ky][1][tq][grp];
        b1[1] = btab[ky][1][tq + 4][grp];

        const int ra = 16 * wid + ky + grp;   // A frag rows: ra, ra+8

        uint32_t acur[4], anxt[4];
        acur[0] = tile[ra][tq];
        acur[1] = tile[ra + 8][tq];
        acur[2] = tile[ra][tq + 4];
        acur[3] = tile[ra + 8][tq + 4];

#pragma unroll
        for (int g = 0; g < 8; g++) {
            const int c = 8 * (g + 1);
            anxt[0] = tile[ra][c + tq];
            anxt[1] = tile[ra + 8][c + tq];
            anxt[2] = tile[ra][c + tq + 4];
            anxt[3] = tile[ra + 8][c + tq + 4];
            mma8(acc[g], acur, b0);     // slice g  with B0
            mma8(acc[g], anxt, b1);     // slice g+1 with B1
            acur[0] = anxt[0]; acur[1] = anxt[1];
            acur[2] = anxt[2]; acur[3] = anxt[3];
        }
    }

    // ---- epilogue: D frag (c0,c1)=(row grp, cols 2tq,2tq+1), (c2,c3)=row grp+8
    float* ob = out + (size_t)b * IMG * IMG;
    const int orow = blockIdx.y * TILE_Y + 16 * wid + grp;
    const int ocol = blockIdx.x * TILE_X + 2 * tq;
#pragma unroll
    for (int g = 0; g < 8; g++) {
        const int c = ocol + 8 * g;
        *reinterpret_cast<float2*>(&ob[(size_t)orow * IMG + c]) =
            make_float2(acc[g][0], acc[g][1]);
        *reinterpret_cast<float2*>(&ob[(size_t)(orow + 8) * IMG + c]) =
            make_float2(acc[g][2], acc[g][3]);
    }
}

extern "C" void kernel_launch(void* const* d_in, const int* in_sizes, int n_in,
                              void* d_out, int out_size)
{
    const float* x = (const float*)d_in[0];   // (64, 512, 512) fp32
    const float* w = (const float*)d_in[1];   // (7, 7) fp32
    float* out = (float*)d_out;

    cudaMemcpyToSymbolAsync(c_w, w, 49 * sizeof(float), 0,
                            cudaMemcpyDeviceToDevice, 0);

    dim3 grid(IMG / TILE_X, IMG / TILE_Y, 64);   // 8 x 4 x 64 = 2048 CTAs
    conv7x7_mma_kernel<<<grid, 256>>>(x, out);
}

// round 13
// speedup vs baseline: 1.3337x; 1.0036x over previous
#include <cuda_runtime.h>
#include <cstdint>
#include <cstddef>

#define IMG 512
#define TILE_Y 128
#define TILE_X 64
#define IN_ROWS 134      // 128 + 6 halo
#define PITCH 76         // smem pitch: 76%32=12 -> conflict-free LDSM phases
#define NV4 18           // 72-col aligned window, col0a = 64*bx - 4

__constant__ float c_w[49];

__device__ __forceinline__ uint32_t f2tf32(float v) {
    uint32_t r;
    asm("cvt.rna.tf32.f32 %0, %1;" : "=r"(r) : "f"(v));
    return r;
}
__device__ __forceinline__ uint32_t smem_u32(const void* p) {
    uint32_t a;
    asm("{ .reg .u64 t; cvta.to.shared.u64 t, %1; cvt.u32.u64 %0, t; }"
        : "=r"(a) : "l"(p));
    return a;
}

// ldmatrix x4: loads the full m16n8k8 tf32 A fragment (4 8x8-b32 quadrants
// viewed as b16 matrices). Lane l supplies row ptr for matrix l>>3.
__device__ __forceinline__ void ldsm4(uint32_t* r, uint32_t addr) {
    asm volatile("ldmatrix.sync.aligned.m8n8.x4.shared.b16 {%0,%1,%2,%3}, [%4];"
                 : "=r"(r[0]), "=r"(r[1]), "=r"(r[2]), "=r"(r[3]) : "r"(addr));
}

// D(16x8,f32) += A(16x8,tf32,row) * B(8x8,tf32,col)
__device__ __forceinline__ void mma8(float* d, const uint32_t* a, const uint32_t* b) {
    asm volatile(
        "mma.sync.aligned.m16n8k8.row.col.f32.tf32.tf32.f32 "
        "{%0,%1,%2,%3}, {%4,%5,%6,%7}, {%8,%9}, {%0,%1,%2,%3};"
        : "+f"(d[0]), "+f"(d[1]), "+f"(d[2]), "+f"(d[3])
        : "r"(a[0]), "r"(a[1]), "r"(a[2]), "r"(a[3]), "r"(b[0]), "r"(b[1]));
}

__global__ __launch_bounds__(256, 4)
void conv7x7_mma_kernel(const float* __restrict__ x, float* __restrict__ out)
{
    __shared__ __align__(16) uint32_t tile[IN_ROWS][PITCH];  // tf32 input window
    __shared__ uint32_t btab[7][2][8][8];                    // tf32 Toeplitz tiles

    const int tid   = threadIdx.x;
    const int b     = blockIdx.z;
    const int row0  = blockIdx.y * TILE_Y - 3;
    const int col0a = blockIdx.x * TILE_X - 4;   // 4-aligned window start

    const float* __restrict__ xb = x + (size_t)b * IMG * IMG;

    // ---- prologue: tile load (float4, zero-pad OOB) + convert to tf32 ----
    for (int i = tid; i < IN_ROWS * NV4; i += 256) {
        int r  = i / NV4;
        int c4 = i - r * NV4;
        int gr = row0 + r;
        int gc = col0a + 4 * c4;
        float4 v = make_float4(0.f, 0.f, 0.f, 0.f);
        if ((unsigned)gr < (unsigned)IMG && (unsigned)gc < (unsigned)IMG)
            v = *reinterpret_cast<const float4*>(&xb[(size_t)gr * IMG + gc]);
        uint4 u = make_uint4(f2tf32(v.x), f2tf32(v.y), f2tf32(v.z), f2tf32(v.w));
        *reinterpret_cast<uint4*>(&tile[r][4 * c4]) = u;
    }

    // ---- Toeplitz B tables: B0[k][n]=w[ky][k-n-1], B1[k][n]=w[ky][k-n+7] ----
    for (int i = tid; i < 7 * 2 * 8 * 8; i += 256) {
        int ky  = i >> 7;
        int var = (i >> 6) & 1;
        int k   = (i >> 3) & 7;
        int n   = i & 7;
        int kx  = var ? (k - n + 7) : (k - n - 1);
        float wv = ((unsigned)kx < 7u) ? c_w[ky * 7 + kx] : 0.0f;
        btab[ky][var][k][n] = f2tf32(wv);
    }
    __syncthreads();

    const int lane = tid & 31;
    const int wid  = tid >> 5;     // warp -> output rows 16*wid .. 16*wid+15
    const int grp  = lane >> 2;    // 0..7
    const int tq   = lane & 3;     // 0..3

    // LDSM lane-pointer geometry: matrix m = lane>>3
    const int mrow = ((lane >> 3) & 1) * 8 + (lane & 7);  // + ra
    const int mcol = (lane >> 4) * 4;

    float acc[8][4] = {};          // 8 n-tiles x 4 fp32 frag regs

    for (int ky = 0; ky < 7; ky++) {
        uint32_t b0[2], b1[2];
        b0[0] = btab[ky][0][tq][grp];
        b0[1] = btab[ky][0][tq + 4][grp];
        b1[0] = btab[ky][1][tq][grp];
        b1[1] = btab[ky][1][tq + 4][grp];

        const int ra = 16 * wid + ky;                 // fragment row base
        uint32_t aptr = smem_u32(&tile[ra + mrow][mcol]);

        uint32_t fcur[4], fnxt[4];
        ldsm4(fcur, aptr);                            // slice 0
#pragma unroll
        for (int g = 0; g < 8; g++) {
            ldsm4(fnxt, aptr + (uint32_t)(g + 1) * 32u);  // slice g+1 (8 cols)
            mma8(acc[g], fcur, b0);
            mma8(acc[g], fnxt, b1);
            fcur[0] = fnxt[0]; fcur[1] = fnxt[1];
            fcur[2] = fnxt[2]; fcur[3] = fnxt[3];
        }
    }

    // ---- epilogue: D frag (c0,c1)=(row grp, cols 2tq,2tq+1), (c2,c3)=row grp+8
    float* ob = out + (size_t)b * IMG * IMG;
    const int orow = blockIdx.y * TILE_Y + 16 * wid + grp;
    const int ocol = blockIdx.x * TILE_X + 2 * tq;
#pragma unroll
    for (int g = 0; g < 8; g++) {
        const int c = ocol + 8 * g;
        *reinterpret_cast<float2*>(&ob[(size_t)orow * IMG + c]) =
            make_float2(acc[g][0], acc[g][1]);
        *reinterpret_cast<float2*>(&ob[(size_t)(orow + 8) * IMG + c]) =
            make_float2(acc[g][2], acc[g][3]);
    }
}

extern "C" void kernel_launch(void* const* d_in, const int* in_sizes, int n_in,
                              void* d_out, int out_size)
{
    const float* x = (const float*)d_in[0];   // (64, 512, 512) fp32
    const float* w = (const float*)d_in[1];   // (7, 7) fp32
    float* out = (float*)d_out;

    cudaMemcpyToSymbolAsync(c_w, w, 49 * sizeof(float), 0,
                            cudaMemcpyDeviceToDevice, 0);

    dim3 grid(IMG / TILE_X, IMG / TILE_Y, 64);   // 8 x 4 x 64 = 2048 CTAs
    conv7x7_mma_kernel<<<grid, 256>>>(x, out);
}